// round 6
// baseline (speedup 1.0000x reference)
#include <cuda_runtime.h>
#include <cuda_bf16.h>

// Shapes: T=64, B=512, D=768, H=12, HD=64
#define T_DIM 64
#define B_DIM 512
#define D_DIM 768
#define H_DIM 12
#define HD_DIM 64
#define ROWS (T_DIM * B_DIM)          // 32768
#define QKV_N (3 * D_DIM)             // 2304

typedef unsigned long long u64;

union f4u { float4 v; u64 u[2]; };

__device__ __forceinline__ u64 pack2(float lo, float hi) {
    u64 r;
    asm("mov.b64 %0, {%1,%2};" : "=l"(r)
        : "r"(__float_as_uint(lo)), "r"(__float_as_uint(hi)));
    return r;
}
__device__ __forceinline__ void ffma2(u64 &d, u64 a, u64 b) {
    asm("fma.rn.f32x2 %0, %1, %2, %0;" : "+l"(d) : "l"(a), "l"(b));
}
__device__ __forceinline__ float2 unpack2(u64 v) {
    unsigned lo, hi;
    asm("mov.b64 {%0,%1}, %2;" : "=r"(lo), "=r"(hi) : "l"(v));
    return make_float2(__uint_as_float(lo), __uint_as_float(hi));
}

// ---------------- scratch (device globals; no allocations) ----------------
__device__ float g_qkv[(size_t)ROWS * QKV_N];   // 302 MB
__device__ float g_ctx[(size_t)ROWS * D_DIM];   // 100 MB
__device__ float g_out[(size_t)ROWS * D_DIM];   // 100 MB
__device__ float g_invn[ROWS];
__device__ float g_svec[T_DIM * D_DIM];

// ---------------- GEMM-NT: C[M,N] = A[M,K] * B[N,K]^T + bias[N] ------------
// BM=BN=128, BK=8, 256 threads, 8x8 microtile (split 4+4), f32x2 inner product.
// Requires M%128==0, N%128==0, K%8==0.
__global__ __launch_bounds__(256)
void gemm_nt_bias(const float* __restrict__ A, const float* __restrict__ B,
                  const float* __restrict__ bias, float* __restrict__ C,
                  int M, int N, int K)
{
    __shared__ __align__(16) float As[8][128];
    __shared__ __align__(16) float Bs[8][128];

    const int tid = threadIdx.x;
    const int m0  = blockIdx.y * 128;
    const int n0  = blockIdx.x * 128;
    const int tx  = tid & 15;
    const int ty  = tid >> 4;
    const int lr  = tid >> 1;        // 0..127: tile row loaded by this thread
    const int lc  = (tid & 1) * 4;   // 0 or 4: k-offset

    const float* Ap = A + (long)(m0 + lr) * K + lc;
    const float* Bp = B + (long)(n0 + lr) * K + lc;

    u64 acc[8][4];
#pragma unroll
    for (int i = 0; i < 8; i++)
#pragma unroll
        for (int j = 0; j < 4; j++) acc[i][j] = 0ull;

    for (int kt = 0; kt < K; kt += 8) {
        float4 av = *(const float4*)(Ap + kt);
        float4 bv = *(const float4*)(Bp + kt);
        As[lc + 0][lr] = av.x; As[lc + 1][lr] = av.y;
        As[lc + 2][lr] = av.z; As[lc + 3][lr] = av.w;
        Bs[lc + 0][lr] = bv.x; Bs[lc + 1][lr] = bv.y;
        Bs[lc + 2][lr] = bv.z; Bs[lc + 3][lr] = bv.w;
        __syncthreads();

#pragma unroll
        for (int k = 0; k < 8; k++) {
            float a[8];
            f4u b0, b1;
            *(float4*)&a[0] = *(const float4*)&As[k][ty * 4];
            *(float4*)&a[4] = *(const float4*)&As[k][64 + ty * 4];
            b0.v = *(const float4*)&Bs[k][tx * 4];
            b1.v = *(const float4*)&Bs[k][64 + tx * 4];
            u64 bp0 = b0.u[0], bp1 = b0.u[1], bp2 = b1.u[0], bp3 = b1.u[1];
#pragma unroll
            for (int i = 0; i < 8; i++) {
                u64 ap = pack2(a[i], a[i]);
                ffma2(acc[i][0], ap, bp0);
                ffma2(acc[i][1], ap, bp1);
                ffma2(acc[i][2], ap, bp2);
                ffma2(acc[i][3], ap, bp3);
            }
        }
        __syncthreads();
    }

    // epilogue
    const int n1 = tx * 4, n2 = 64 + tx * 4;
    float bia0 = bias[n0 + n1 + 0], bia1 = bias[n0 + n1 + 1];
    float bia2 = bias[n0 + n1 + 2], bia3 = bias[n0 + n1 + 3];
    float bib0 = bias[n0 + n2 + 0], bib1 = bias[n0 + n2 + 1];
    float bib2 = bias[n0 + n2 + 2], bib3 = bias[n0 + n2 + 3];
#pragma unroll
    for (int i = 0; i < 8; i++) {
        int m = m0 + ((i < 4) ? (ty * 4 + i) : (64 + ty * 4 + (i - 4)));
        float* crow = C + (long)m * N + n0;
        float2 c0 = unpack2(acc[i][0]);
        float2 c1 = unpack2(acc[i][1]);
        float2 c2 = unpack2(acc[i][2]);
        float2 c3 = unpack2(acc[i][3]);
        float4 o1 = make_float4(c0.x + bia0, c0.y + bia1, c1.x + bia2, c1.y + bia3);
        float4 o2 = make_float4(c2.x + bib0, c2.y + bib1, c3.x + bib2, c3.y + bib3);
        *(float4*)(crow + n1) = o1;
        *(float4*)(crow + n2) = o2;
    }
}

// ---------------- Attention: per (t,h) softmax over B axis ----------------
// grid (4, H, T), block 128. Thread owns one query row (q,o in registers).
// Scores are small (|s|<~2), so exp without max-subtraction is exact-safe.
__global__ __launch_bounds__(128)
void attn_kernel(const float* __restrict__ qkv, float* __restrict__ ctx)
{
    __shared__ __align__(16) float ks[64][64];
    __shared__ __align__(16) float vs[64][64];

    const int t = blockIdx.z, h = blockIdx.y, qb = blockIdx.x;
    const int tid = threadIdx.x;
    const int r = qb * 128 + tid;                 // query row in [0,512)
    const long rs = QKV_N;
    const float* base = qkv + (long)t * B_DIM * rs;

    u64 q2[32], o2[32];
    {
        const float* qrow = base + (long)r * rs + h * HD_DIM;
#pragma unroll
        for (int d = 0; d < 16; d++) {
            f4u v; v.v = *(const float4*)(qrow + d * 4);
            q2[d * 2]     = v.u[0];
            q2[d * 2 + 1] = v.u[1];
        }
    }
#pragma unroll
    for (int i = 0; i < 32; i++) o2[i] = 0ull;
    float esum = 0.f;

    for (int kb = 0; kb < 8; kb++) {
        __syncthreads();
        // cooperative load of 64x64 K and V tiles (coalesced)
#pragma unroll
        for (int i = 0; i < 8; i++) {
            int lin = i * 512 + tid * 4;
            int row = lin >> 6, col = lin & 63;
            const float* src = base + (long)(kb * 64 + row) * rs + h * HD_DIM + col;
            *(float4*)&ks[row][col] = *(const float4*)(src + D_DIM);       // K
            *(float4*)&vs[row][col] = *(const float4*)(src + 2 * D_DIM);   // V
        }
        __syncthreads();

        for (int j = 0; j < 64; j++) {
            u64 sA = 0ull, sB = 0ull, sC = 0ull, sD = 0ull;
#pragma unroll
            for (int d = 0; d < 16; d += 2) {
                f4u ka; ka.v = *(const float4*)&ks[j][d * 4];
                f4u kb2; kb2.v = *(const float4*)&ks[j][d * 4 + 4];
                ffma2(sA, q2[d * 2],     ka.u[0]);
                ffma2(sB, q2[d * 2 + 1], ka.u[1]);
                ffma2(sC, q2[d * 2 + 2], kb2.u[0]);
                ffma2(sD, q2[d * 2 + 3], kb2.u[1]);
            }
            float2 h0 = unpack2(sA), h1 = unpack2(sB), h2 = unpack2(sC), h3 = unpack2(sD);
            float sc = (h0.x + h0.y) + (h1.x + h1.y) + (h2.x + h2.y) + (h3.x + h3.y);
            float e = __expf(sc * 0.125f);   // 1/sqrt(64)
            esum += e;
            u64 e2 = pack2(e, e);
#pragma unroll
            for (int d = 0; d < 16; d++) {
                f4u vv; vv.v = *(const float4*)&vs[j][d * 4];
                ffma2(o2[d * 2],     e2, vv.u[0]);
                ffma2(o2[d * 2 + 1], e2, vv.u[1]);
            }
        }
    }

    float inv = 1.f / esum;
    float* crow = ctx + ((long)t * B_DIM + r) * D_DIM + h * HD_DIM;
#pragma unroll
    for (int d = 0; d < 16; d++) {
        float2 a = unpack2(o2[d * 2]);
        float2 b = unpack2(o2[d * 2 + 1]);
        float4 w = make_float4(a.x * inv, a.y * inv, b.x * inv, b.y * inv);
        *(float4*)(crow + d * 4) = w;
    }
}

// ---------------- epilogue kernels ----------------
// inv-norms: one warp per row (768 elems)
__global__ __launch_bounds__(256)
void rownorm_kernel(const float* __restrict__ o, float* __restrict__ invn)
{
    int row = blockIdx.x * 8 + (threadIdx.x >> 5);
    int lane = threadIdx.x & 31;
    const float* p = o + (long)row * D_DIM;
    float ss = 0.f;
#pragma unroll
    for (int k = 0; k < 6; k++) {
        float4 v = *(const float4*)(p + lane * 4 + k * 128);
        ss += v.x * v.x + v.y * v.y + v.z * v.z + v.w * v.w;
    }
#pragma unroll
    for (int off = 16; off; off >>= 1) ss += __shfl_xor_sync(0xffffffffu, ss, off);
    if (lane == 0) invn[row] = 1.f / fmaxf(sqrtf(ss), 1e-8f);
}

// s[t][d] = sum_b out[t,b,d] * invn[t,b]
__global__ __launch_bounds__(256)
void meanvec_kernel(const float* __restrict__ o, const float* __restrict__ invn,
                    float* __restrict__ svec)
{
    int t = blockIdx.y;
    int d = blockIdx.x * 256 + threadIdx.x;
    const float* p = o + (long)t * B_DIM * D_DIM + d;
    const float* iv = invn + t * B_DIM;
    float s = 0.f;
#pragma unroll 8
    for (int b = 0; b < B_DIM; b++) s += p[(long)b * D_DIM] * iv[b];
    svec[t * D_DIM + d] = s;
}

// adj[t,b] = (s[t] . out[t,b,:]) * invn[t,b] / B
__global__ __launch_bounds__(256)
void adj_kernel(const float* __restrict__ o, const float* __restrict__ invn,
                const float* __restrict__ svec, float* __restrict__ adj)
{
    int row = blockIdx.x * 8 + (threadIdx.x >> 5);
    int lane = threadIdx.x & 31;
    int t = row >> 9;
    const float* p = o + (long)row * D_DIM;
    const float* sv = svec + t * D_DIM;
    float acc = 0.f;
#pragma unroll
    for (int k = 0; k < 6; k++) {
        float4 v = *(const float4*)(p + lane * 4 + k * 128);
        float4 s = *(const float4*)(sv + lane * 4 + k * 128);
        acc += v.x * s.x + v.y * s.y + v.z * s.z + v.w * s.w;
    }
#pragma unroll
    for (int off = 16; off; off >>= 1) acc += __shfl_xor_sync(0xffffffffu, acc, off);
    if (lane == 0) adj[row] = acc * invn[row] * (1.0f / (float)B_DIM);
}

// ---------------- launch ----------------
extern "C" void kernel_launch(void* const* d_in, const int* in_sizes, int n_in,
                              void* d_out, int out_size)
{
    const float* x  = (const float*)d_in[0];   // node_embs (T,B,D)
    const float* w1 = (const float*)d_in[1];   // in_proj_w (3D,D)
    const float* b1 = (const float*)d_in[2];   // in_proj_b (3D)
    const float* w2 = (const float*)d_in[3];   // out_proj_w (D,D)
    const float* b2 = (const float*)d_in[4];   // out_proj_b (D)
    float* adj = (float*)d_out;                // (T,B,1)

    float *qkv, *ctx, *outb, *invn, *svec;
    cudaGetSymbolAddress((void**)&qkv,  g_qkv);
    cudaGetSymbolAddress((void**)&ctx,  g_ctx);
    cudaGetSymbolAddress((void**)&outb, g_out);
    cudaGetSymbolAddress((void**)&invn, g_invn);
    cudaGetSymbolAddress((void**)&svec, g_svec);

    // 1) qkv = x @ W1^T + b1   (M=32768, N=2304, K=768)
    gemm_nt_bias<<<dim3(QKV_N / 128, ROWS / 128), 256>>>(x, w1, b1, qkv, ROWS, QKV_N, D_DIM);
    // 2) attention -> ctx
    attn_kernel<<<dim3(4, H_DIM, T_DIM), 128>>>(qkv, ctx);
    // 3) out = ctx @ W2^T + b2  (M=32768, N=768, K=768)
    gemm_nt_bias<<<dim3(D_DIM / 128, ROWS / 128), 256>>>(ctx, w2, b2, outb, ROWS, D_DIM, D_DIM);
    // 4) row inverse norms
    rownorm_kernel<<<ROWS / 8, 256>>>(outb, invn);
    // 5) per-t mean normalized vector
    meanvec_kernel<<<dim3(D_DIM / 256, T_DIM), 256>>>(outb, invn, svec);
    // 6) adj = (s . out_row) * invn / B
    adj_kernel<<<ROWS / 8, 256>>>(outb, invn, svec, adj);
}

// round 11
// speedup vs baseline: 1.8052x; 1.8052x over previous
#include <cuda_runtime.h>
#include <cuda_bf16.h>
#include <cstdint>

// Shapes: T=64, B=512, D=768, H=12, HD=64
#define T_DIM 64
#define B_DIM 512
#define D_DIM 768
#define H_DIM 12
#define HD_DIM 64
#define ROWS (T_DIM * B_DIM)          // 32768
#define QKV_N (3 * D_DIM)             // 2304

typedef unsigned long long u64;
typedef __nv_bfloat16 bf16;

union f4u { float4 v; u64 u[2]; };

__device__ __forceinline__ u64 pack2(float lo, float hi) {
    u64 r;
    asm("mov.b64 %0, {%1,%2};" : "=l"(r)
        : "r"(__float_as_uint(lo)), "r"(__float_as_uint(hi)));
    return r;
}
__device__ __forceinline__ void ffma2(u64 &d, u64 a, u64 b) {
    asm("fma.rn.f32x2 %0, %1, %2, %0;" : "+l"(d) : "l"(a), "l"(b));
}
__device__ __forceinline__ float2 unpack2(u64 v) {
    unsigned lo, hi;
    asm("mov.b64 {%0,%1}, %2;" : "=r"(lo), "=r"(hi) : "l"(v));
    return make_float2(__uint_as_float(lo), __uint_as_float(hi));
}

__device__ __forceinline__ uint32_t smem_to_u32(const void* p) {
    uint32_t a;
    asm("{ .reg .u64 t; cvta.to.shared.u64 t, %1; cvt.u32.u64 %0, t; }"
        : "=r"(a) : "l"(p));
    return a;
}

#define SWZ(x) ((x) ^ (((x) >> 3) & 0x70))

__device__ __forceinline__ void cp16(uint32_t dst, const void* src) {
    asm volatile("cp.async.cg.shared.global [%0], [%1], 16;"
                 :: "r"(dst), "l"(src));
}
__device__ __forceinline__ void cp_commit() {
    asm volatile("cp.async.commit_group;");
}
__device__ __forceinline__ void cp_wait0() {
    asm volatile("cp.async.wait_group 0;");
}

__device__ __forceinline__ void ldmx4(uint32_t* r, uint32_t addr) {
    asm volatile("ldmatrix.sync.aligned.m8n8.x4.shared.b16 {%0,%1,%2,%3}, [%4];"
                 : "=r"(r[0]), "=r"(r[1]), "=r"(r[2]), "=r"(r[3]) : "r"(addr));
}
__device__ __forceinline__ void mma16816(float* d, const uint32_t* a,
                                         uint32_t b0, uint32_t b1) {
    asm volatile(
        "mma.sync.aligned.m16n8k16.row.col.f32.bf16.bf16.f32 "
        "{%0,%1,%2,%3}, {%4,%5,%6,%7}, {%8,%9}, {%0,%1,%2,%3};"
        : "+f"(d[0]), "+f"(d[1]), "+f"(d[2]), "+f"(d[3])
        : "r"(a[0]), "r"(a[1]), "r"(a[2]), "r"(a[3]), "r"(b0), "r"(b1));
}

// ---------------- scratch (device globals; no allocations) ----------------
__device__ float g_qkv[(size_t)ROWS * QKV_N];
__device__ float g_ctx[(size_t)ROWS * D_DIM];
__device__ float g_out[(size_t)ROWS * D_DIM];
__device__ float g_invn[ROWS];
__device__ float g_svec[T_DIM * D_DIM];
// bf16 hi/lo splits
__device__ __align__(16) bf16 g_xh[(size_t)ROWS * D_DIM];
__device__ __align__(16) bf16 g_xl[(size_t)ROWS * D_DIM];
__device__ __align__(16) bf16 g_ch[(size_t)ROWS * D_DIM];
__device__ __align__(16) bf16 g_cl[(size_t)ROWS * D_DIM];
__device__ __align__(16) bf16 g_w1h[(size_t)QKV_N * D_DIM];
__device__ __align__(16) bf16 g_w1l[(size_t)QKV_N * D_DIM];
__device__ __align__(16) bf16 g_w2h[(size_t)D_DIM * D_DIM];
__device__ __align__(16) bf16 g_w2l[(size_t)D_DIM * D_DIM];

// ---------------- fp32 -> bf16 hi/lo split ----------------
__global__ __launch_bounds__(256)
void cvt_hilo(const float* __restrict__ x, bf16* __restrict__ h,
              bf16* __restrict__ l, int n4)
{
    int i = blockIdx.x * 256 + threadIdx.x;
    if (i >= n4) return;
    float4 v = ((const float4*)x)[i];
    bf16 h0 = __float2bfloat16_rn(v.x);
    bf16 h1 = __float2bfloat16_rn(v.y);
    bf16 h2 = __float2bfloat16_rn(v.z);
    bf16 h3 = __float2bfloat16_rn(v.w);
    bf16 l0 = __float2bfloat16_rn(v.x - __bfloat162float(h0));
    bf16 l1 = __float2bfloat16_rn(v.y - __bfloat162float(h1));
    bf16 l2 = __float2bfloat16_rn(v.z - __bfloat162float(h2));
    bf16 l3 = __float2bfloat16_rn(v.w - __bfloat162float(h3));
    union { bf16 b[4]; uint2 u; } ph, pl;
    ph.b[0] = h0; ph.b[1] = h1; ph.b[2] = h2; ph.b[3] = h3;
    pl.b[0] = l0; pl.b[1] = l1; pl.b[2] = l2; pl.b[3] = l3;
    ((uint2*)h)[i] = ph.u;
    ((uint2*)l)[i] = pl.u;
}

// ------------- mma.sync bf16 GEMM-NT: C = A*B^T + bias, 3x-split ----------
// Virtual K = 3*K via segments (Ah,Bh), (Ah,Bl), (Al,Bh).
// Tile 128x128, BK=64, 256 threads (8 warps, 2x4), warp tile 64x32.
// SMEM per buffer: A 16KB + B 16KB, double-buffered (64KB); epilogue reuses
// smem as 128 x 132 f32 staging (67584 B).
#define GEMM_SMEM_BYTES (132 * 128 * 4)

__global__ __launch_bounds__(256)
void gemm_tc(const bf16* __restrict__ Agh, const bf16* __restrict__ Agl,
             const bf16* __restrict__ Bgh, const bf16* __restrict__ Bgl,
             const float* __restrict__ bias, float* __restrict__ C,
             int N, int K)
{
    extern __shared__ __align__(1024) char smem[];
    const uint32_t sb = smem_to_u32(smem);
    const int tid = threadIdx.x;
    const int wid = tid >> 5, lane = tid & 31;
    const int wm = wid >> 2, wn = wid & 3;       // 2 x 4 warp grid
    const int m0 = blockIdx.y * 128, n0 = blockIdx.x * 128;

    const int NSEG_T = K / 64;                   // tiles per segment (12)
    const int NT = 3 * NSEG_T;                   // 36

    float d[4][4][4];
#pragma unroll
    for (int i = 0; i < 4; i++)
#pragma unroll
        for (int j = 0; j < 4; j++)
#pragma unroll
            for (int k = 0; k < 4; k++) d[i][j][k] = 0.f;

    // loader indices: 8 lanes per 128B row
    const int lrow = tid >> 3, lch = tid & 7;

    // ---- issue loads for tile 'it' into buffer b ----
    auto load_tile = [&](int it, int b) {
        int seg = it / NSEG_T;
        long koff = (long)(it - seg * NSEG_T) * 64;
        const bf16* As_ = (seg < 2) ? Agh : Agl;
        const bf16* Bs_ = (seg == 1) ? Bgl : Bgh;
        uint32_t tA = sb + b * 32768;
        uint32_t tB = tA + 16384;
#pragma unroll
        for (int p = 0; p < 4; p++) {
            int row = lrow + p * 32;
            uint32_t off = SWZ((uint32_t)(row * 128 + lch * 16));
            cp16(tA + off, As_ + (long)(m0 + row) * K + koff + lch * 8);
        }
#pragma unroll
        for (int p = 0; p < 4; p++) {
            int row = lrow + p * 32;
            uint32_t off = SWZ((uint32_t)(row * 128 + lch * 16));
            cp16(tB + off, Bs_ + (long)(n0 + row) * K + koff + lch * 8);
        }
        cp_commit();
    };

    load_tile(0, 0);

    for (int it = 0; it < NT; ++it) {
        cp_wait0();
        __syncthreads();
        if (it + 1 < NT) load_tile(it + 1, (it + 1) & 1);

        uint32_t tA = sb + (it & 1) * 32768;
        uint32_t tB = tA + 16384;

#pragma unroll
        for (int ks = 0; ks < 4; ks++) {
            uint32_t a[4][4];
#pragma unroll
            for (int mi = 0; mi < 4; mi++) {
                int row = wm * 64 + mi * 16 + (lane & 15);
                uint32_t off = (uint32_t)(row * 128 + (2 * ks + (lane >> 4)) * 16);
                ldmx4(a[mi], tA + SWZ(off));
            }
            uint32_t b[2][4];
#pragma unroll
            for (int nj = 0; nj < 2; nj++) {
                int row = wn * 32 + nj * 16 + (lane & 7) + ((lane >> 4) << 3);
                uint32_t off = (uint32_t)(row * 128 + (2 * ks + ((lane >> 3) & 1)) * 16);
                ldmx4(b[nj], tB + SWZ(off));
            }
#pragma unroll
            for (int mi = 0; mi < 4; mi++)
#pragma unroll
                for (int ni = 0; ni < 4; ni++)
                    mma16816(d[mi][ni], a[mi],
                             b[ni >> 1][(ni & 1) * 2], b[ni >> 1][(ni & 1) * 2 + 1]);
        }
        __syncthreads();
    }

    // ---- epilogue: stage to smem, coalesced fp32 stores + bias ----
    float* sf = (float*)smem;                    // 128 x 132
#pragma unroll
    for (int mi = 0; mi < 4; mi++)
#pragma unroll
        for (int ni = 0; ni < 4; ni++) {
            int row = wm * 64 + mi * 16 + (lane >> 2);
            int col = wn * 32 + ni * 8 + 2 * (lane & 3);
            *(float2*)&sf[row * 132 + col]       = make_float2(d[mi][ni][0], d[mi][ni][1]);
            *(float2*)&sf[(row + 8) * 132 + col] = make_float2(d[mi][ni][2], d[mi][ni][3]);
        }
    __syncthreads();
#pragma unroll
    for (int p = 0; p < 16; p++) {
        int lin = p * 256 + tid;
        int row = lin >> 5, q = (lin & 31) * 4;
        const float* sr = sf + row * 132 + q;
        int n = n0 + q;
        float4 o;
        o.x = sr[0] + bias[n + 0];
        o.y = sr[1] + bias[n + 1];
        o.z = sr[2] + bias[n + 2];
        o.w = sr[3] + bias[n + 3];
        *(float4*)(C + (long)(m0 + row) * N + n) = o;
    }
}

// ---------------- Attention: per (t,h) softmax over B axis ----------------
__global__ __launch_bounds__(128)
void attn_kernel(const float* __restrict__ qkv, float* __restrict__ ctx)
{
    __shared__ __align__(16) float ks[64][64];
    __shared__ __align__(16) float vs[64][64];

    const int t = blockIdx.z, h = blockIdx.y, qb = blockIdx.x;
    const int tid = threadIdx.x;
    const int r = qb * 128 + tid;
    const long rs = QKV_N;
    const float* base = qkv + (long)t * B_DIM * rs;

    u64 q2[32], o2[32];
    {
        const float* qrow = base + (long)r * rs + h * HD_DIM;
#pragma unroll
        for (int d = 0; d < 16; d++) {
            f4u v; v.v = *(const float4*)(qrow + d * 4);
            q2[d * 2]     = v.u[0];
            q2[d * 2 + 1] = v.u[1];
        }
    }
#pragma unroll
    for (int i = 0; i < 32; i++) o2[i] = 0ull;
    float esum = 0.f;

    for (int kb = 0; kb < 8; kb++) {
        __syncthreads();
#pragma unroll
        for (int i = 0; i < 8; i++) {
            int lin = i * 512 + tid * 4;
            int row = lin >> 6, col = lin & 63;
            const float* src = base + (long)(kb * 64 + row) * rs + h * HD_DIM + col;
            *(float4*)&ks[row][col] = *(const float4*)(src + D_DIM);
            *(float4*)&vs[row][col] = *(const float4*)(src + 2 * D_DIM);
        }
        __syncthreads();

        for (int j = 0; j < 64; j++) {
            u64 sA = 0ull, sB = 0ull, sC = 0ull, sD = 0ull;
#pragma unroll
            for (int d = 0; d < 16; d += 2) {
                f4u ka; ka.v = *(const float4*)&ks[j][d * 4];
                f4u kb2; kb2.v = *(const float4*)&ks[j][d * 4 + 4];
                ffma2(sA, q2[d * 2],     ka.u[0]);
                ffma2(sB, q2[d * 2 + 1], ka.u[1]);
                ffma2(sC, q2[d * 2 + 2], kb2.u[0]);
                ffma2(sD, q2[d * 2 + 3], kb2.u[1]);
            }
            float2 h0 = unpack2(sA), h1 = unpack2(sB), h2 = unpack2(sC), h3 = unpack2(sD);
            float sc = (h0.x + h0.y) + (h1.x + h1.y) + (h2.x + h2.y) + (h3.x + h3.y);
            float e = __expf(sc * 0.125f);
            esum += e;
            u64 e2 = pack2(e, e);
#pragma unroll
            for (int d = 0; d < 16; d++) {
                f4u vv; vv.v = *(const float4*)&vs[j][d * 4];
                ffma2(o2[d * 2],     e2, vv.u[0]);
                ffma2(o2[d * 2 + 1], e2, vv.u[1]);
            }
        }
    }

    float inv = 1.f / esum;
    float* crow = ctx + ((long)t * B_DIM + r) * D_DIM + h * HD_DIM;
#pragma unroll
    for (int d = 0; d < 16; d++) {
        float2 a = unpack2(o2[d * 2]);
        float2 b = unpack2(o2[d * 2 + 1]);
        float4 w = make_float4(a.x * inv, a.y * inv, b.x * inv, b.y * inv);
        *(float4*)(crow + d * 4) = w;
    }
}

// ---------------- epilogue kernels ----------------
__global__ __launch_bounds__(256)
void rownorm_kernel(const float* __restrict__ o, float* __restrict__ invn)
{
    int row = blockIdx.x * 8 + (threadIdx.x >> 5);
    int lane = threadIdx.x & 31;
    const float* p = o + (long)row * D_DIM;
    float ss = 0.f;
#pragma unroll
    for (int k = 0; k < 6; k++) {
        float4 v = *(const float4*)(p + lane * 4 + k * 128);
        ss += v.x * v.x + v.y * v.y + v.z * v.z + v.w * v.w;
    }
#pragma unroll
    for (int off = 16; off; off >>= 1) ss += __shfl_xor_sync(0xffffffffu, ss, off);
    if (lane == 0) invn[row] = 1.f / fmaxf(sqrtf(ss), 1e-8f);
}

__global__ __launch_bounds__(256)
void meanvec_kernel(const float* __restrict__ o, const float* __restrict__ invn,
                    float* __restrict__ svec)
{
    int t = blockIdx.y;
    int d = blockIdx.x * 256 + threadIdx.x;
    const float* p = o + (long)t * B_DIM * D_DIM + d;
    const float* iv = invn + t * B_DIM;
    float s = 0.f;
#pragma unroll 8
    for (int b = 0; b < B_DIM; b++) s += p[(long)b * D_DIM] * iv[b];
    svec[t * D_DIM + d] = s;
}

__global__ __launch_bounds__(256)
void adj_kernel(const float* __restrict__ o, const float* __restrict__ invn,
                const float* __restrict__ svec, float* __restrict__ adj)
{
    int row = blockIdx.x * 8 + (threadIdx.x >> 5);
    int lane = threadIdx.x & 31;
    int t = row >> 9;
    const float* p = o + (long)row * D_DIM;
    const float* sv = svec + t * D_DIM;
    float acc = 0.f;
#pragma unroll
    for (int k = 0; k < 6; k++) {
        float4 v = *(const float4*)(p + lane * 4 + k * 128);
        float4 s = *(const float4*)(sv + lane * 4 + k * 128);
        acc += v.x * s.x + v.y * s.y + v.z * s.z + v.w * s.w;
    }
#pragma unroll
    for (int off = 16; off; off >>= 1) acc += __shfl_xor_sync(0xffffffffu, acc, off);
    if (lane == 0) adj[row] = acc * invn[row] * (1.0f / (float)B_DIM);
}

// ---------------- launch ----------------
extern "C" void kernel_launch(void* const* d_in, const int* in_sizes, int n_in,
                              void* d_out, int out_size)
{
    const float* x  = (const float*)d_in[0];   // node_embs (T,B,D)
    const float* w1 = (const float*)d_in[1];   // in_proj_w (3D,D)
    const float* b1 = (const float*)d_in[2];   // in_proj_b (3D)
    const float* w2 = (const float*)d_in[3];   // out_proj_w (D,D)
    const float* b2 = (const float*)d_in[4];   // out_proj_b (D)
    float* adj = (float*)d_out;                // (T,B,1)

    float *qkv, *ctx, *outb, *invn, *svec;
    bf16 *xh, *xl, *chh, *cl, *w1h, *w1l, *w2h, *w2l;
    cudaGetSymbolAddress((void**)&qkv,  g_qkv);
    cudaGetSymbolAddress((void**)&ctx,  g_ctx);
    cudaGetSymbolAddress((void**)&outb, g_out);
    cudaGetSymbolAddress((void**)&invn, g_invn);
    cudaGetSymbolAddress((void**)&svec, g_svec);
    cudaGetSymbolAddress((void**)&xh,  g_xh);
    cudaGetSymbolAddress((void**)&xl,  g_xl);
    cudaGetSymbolAddress((void**)&chh, g_ch);
    cudaGetSymbolAddress((void**)&cl,  g_cl);
    cudaGetSymbolAddress((void**)&w1h, g_w1h);
    cudaGetSymbolAddress((void**)&w1l, g_w1l);
    cudaGetSymbolAddress((void**)&w2h, g_w2h);
    cudaGetSymbolAddress((void**)&w2l, g_w2l);

    cudaFuncSetAttribute(gemm_tc, cudaFuncAttributeMaxDynamicSharedMemorySize,
                         GEMM_SMEM_BYTES);

    // 0) bf16 hi/lo splits of x, w1, w2
    {
        int n4 = ROWS * D_DIM / 4;
        cvt_hilo<<<(n4 + 255) / 256, 256>>>(x, xh, xl, n4);
    }
    {
        int n4 = QKV_N * D_DIM / 4;
        cvt_hilo<<<(n4 + 255) / 256, 256>>>(w1, w1h, w1l, n4);
    }
    {
        int n4 = D_DIM * D_DIM / 4;
        cvt_hilo<<<(n4 + 255) / 256, 256>>>(w2, w2h, w2l, n4);
    }

    // 1) qkv = x @ W1^T + b1   (M=32768, N=2304, K=768) — mma.sync bf16 x3
    gemm_tc<<<dim3(QKV_N / 128, ROWS / 128), 256, GEMM_SMEM_BYTES>>>(
        xh, xl, w1h, w1l, b1, qkv, QKV_N, D_DIM);

    // 2) attention -> ctx (fp32 SIMT)
    attn_kernel<<<dim3(4, H_DIM, T_DIM), 128>>>(qkv, ctx);

    // 2b) split ctx
    {
        int n4 = ROWS * D_DIM / 4;
        cvt_hilo<<<(n4 + 255) / 256, 256>>>(ctx, chh, cl, n4);
    }

    // 3) out = ctx @ W2^T + b2  (M=32768, N=768, K=768) — mma.sync bf16 x3
    gemm_tc<<<dim3(D_DIM / 128, ROWS / 128), 256, GEMM_SMEM_BYTES>>>(
        chh, cl, w2h, w2l, b2, outb, D_DIM, D_DIM);

    // 4-6) cosine-sim epilogue (collapsed via mean-vector identity)
    rownorm_kernel<<<ROWS / 8, 256>>>(outb, invn);
    meanvec_kernel<<<dim3(D_DIM / 256, T_DIM), 256>>>(outb, invn, svec);
    adj_kernel<<<ROWS / 8, 256>>>(outb, invn, svec, adj);
}

// round 14
// speedup vs baseline: 1.9907x; 1.1028x over previous
#include <cuda_runtime.h>
#include <cuda_bf16.h>
#include <cstdint>

// Shapes: T=64, B=512, D=768, H=12, HD=64
#define T_DIM 64
#define B_DIM 512
#define D_DIM 768
#define H_DIM 12
#define HD_DIM 64
#define ROWS (T_DIM * B_DIM)          // 32768
#define QKV_N (3 * D_DIM)             // 2304

typedef unsigned long long u64;
typedef __nv_bfloat16 bf16;

__device__ __forceinline__ uint32_t smem_to_u32(const void* p) {
    uint32_t a;
    asm("{ .reg .u64 t; cvta.to.shared.u64 t, %1; cvt.u32.u64 %0, t; }"
        : "=r"(a) : "l"(p));
    return a;
}

#define SWZ(x) ((x) ^ (((x) >> 3) & 0x70))

__device__ __forceinline__ void cp16(uint32_t dst, const void* src) {
    asm volatile("cp.async.cg.shared.global [%0], [%1], 16;"
                 :: "r"(dst), "l"(src));
}
__device__ __forceinline__ void cp_commit() {
    asm volatile("cp.async.commit_group;");
}
__device__ __forceinline__ void cp_wait0() {
    asm volatile("cp.async.wait_group 0;");
}

__device__ __forceinline__ void ldmx4(uint32_t* r, uint32_t addr) {
    asm volatile("ldmatrix.sync.aligned.m8n8.x4.shared.b16 {%0,%1,%2,%3}, [%4];"
                 : "=r"(r[0]), "=r"(r[1]), "=r"(r[2]), "=r"(r[3]) : "r"(addr));
}
__device__ __forceinline__ void ldmx4t(uint32_t* r, uint32_t addr) {
    asm volatile("ldmatrix.sync.aligned.m8n8.x4.trans.shared.b16 {%0,%1,%2,%3}, [%4];"
                 : "=r"(r[0]), "=r"(r[1]), "=r"(r[2]), "=r"(r[3]) : "r"(addr));
}
__device__ __forceinline__ void mma16816(float* d, const uint32_t* a,
                                         uint32_t b0, uint32_t b1) {
    asm volatile(
        "mma.sync.aligned.m16n8k16.row.col.f32.bf16.bf16.f32 "
        "{%0,%1,%2,%3}, {%4,%5,%6,%7}, {%8,%9}, {%0,%1,%2,%3};"
        : "+f"(d[0]), "+f"(d[1]), "+f"(d[2]), "+f"(d[3])
        : "r"(a[0]), "r"(a[1]), "r"(a[2]), "r"(a[3]), "r"(b0), "r"(b1));
}

__device__ __forceinline__ float fast_ex2(float x) {
    float r;
    asm("ex2.approx.ftz.f32 %0, %1;" : "=f"(r) : "f"(x));
    return r;
}
// split two floats into packed-bf16 hi and lo words
__device__ __forceinline__ void hilo_pack(float x, float y, uint32_t& hw, uint32_t& lw) {
    union { bf16 b[2]; uint32_t u; } H, L;
    H.b[0] = __float2bfloat16_rn(x);
    H.b[1] = __float2bfloat16_rn(y);
    L.b[0] = __float2bfloat16_rn(x - __bfloat162float(H.b[0]));
    L.b[1] = __float2bfloat16_rn(y - __bfloat162float(H.b[1]));
    hw = H.u; lw = L.u;
}

// ---------------- scratch (device globals; no allocations) ----------------
__device__ float g_out[(size_t)ROWS * D_DIM];
__device__ float g_invn[ROWS];
__device__ float g_svec[T_DIM * D_DIM];
// bf16 hi/lo buffers
__device__ __align__(16) bf16 g_qkvh[(size_t)ROWS * QKV_N];  // 151 MB
__device__ __align__(16) bf16 g_qkvl[(size_t)ROWS * QKV_N];  // 151 MB
__device__ __align__(16) bf16 g_xh[(size_t)ROWS * D_DIM];
__device__ __align__(16) bf16 g_xl[(size_t)ROWS * D_DIM];
__device__ __align__(16) bf16 g_ch[(size_t)ROWS * D_DIM];
__device__ __align__(16) bf16 g_cl[(size_t)ROWS * D_DIM];
__device__ __align__(16) bf16 g_w1h[(size_t)QKV_N * D_DIM];
__device__ __align__(16) bf16 g_w1l[(size_t)QKV_N * D_DIM];
__device__ __align__(16) bf16 g_w2h[(size_t)D_DIM * D_DIM];
__device__ __align__(16) bf16 g_w2l[(size_t)D_DIM * D_DIM];

// ---------------- fp32 -> bf16 hi/lo split ----------------
__global__ __launch_bounds__(256)
void cvt_hilo(const float* __restrict__ x, bf16* __restrict__ h,
              bf16* __restrict__ l, int n4)
{
    int i = blockIdx.x * 256 + threadIdx.x;
    if (i >= n4) return;
    float4 v = ((const float4*)x)[i];
    union { bf16 b[4]; uint2 u; } ph, pl;
    ph.b[0] = __float2bfloat16_rn(v.x);
    ph.b[1] = __float2bfloat16_rn(v.y);
    ph.b[2] = __float2bfloat16_rn(v.z);
    ph.b[3] = __float2bfloat16_rn(v.w);
    pl.b[0] = __float2bfloat16_rn(v.x - __bfloat162float(ph.b[0]));
    pl.b[1] = __float2bfloat16_rn(v.y - __bfloat162float(ph.b[1]));
    pl.b[2] = __float2bfloat16_rn(v.z - __bfloat162float(ph.b[2]));
    pl.b[3] = __float2bfloat16_rn(v.w - __bfloat162float(ph.b[3]));
    ((uint2*)h)[i] = ph.u;
    ((uint2*)l)[i] = pl.u;
}

// ------------- mma.sync bf16 GEMM-NT: C = A*B^T + bias, 3x-split ----------
// Virtual K = 3*K via segments (Ah,Bh), (Ah,Bl), (Al,Bh).
// Tile 128x128, BK=64, 256 threads (8 warps, 2x4), warp tile 64x32.
// Output: fp32 C (if Chi==null) or bf16 hi/lo pair (Chi/Clo).
#define GEMM_SMEM_BYTES (132 * 128 * 4)

__global__ __launch_bounds__(256)
void gemm_tc(const bf16* __restrict__ Agh, const bf16* __restrict__ Agl,
             const bf16* __restrict__ Bgh, const bf16* __restrict__ Bgl,
             const float* __restrict__ bias, float* __restrict__ C,
             bf16* __restrict__ Chi, bf16* __restrict__ Clo,
             int N, int K)
{
    extern __shared__ __align__(1024) char smem[];
    const uint32_t sb = smem_to_u32(smem);
    const int tid = threadIdx.x;
    const int wid = tid >> 5, lane = tid & 31;
    const int wm = wid >> 2, wn = wid & 3;       // 2 x 4 warp grid
    const int m0 = blockIdx.y * 128, n0 = blockIdx.x * 128;

    const int NSEG_T = K / 64;
    const int NT = 3 * NSEG_T;

    float d[4][4][4];
#pragma unroll
    for (int i = 0; i < 4; i++)
#pragma unroll
        for (int j = 0; j < 4; j++)
#pragma unroll
            for (int k = 0; k < 4; k++) d[i][j][k] = 0.f;

    const int lrow = tid >> 3, lch = tid & 7;

    auto load_tile = [&](int it, int b) {
        int seg = it / NSEG_T;
        long koff = (long)(it - seg * NSEG_T) * 64;
        const bf16* As_ = (seg < 2) ? Agh : Agl;
        const bf16* Bs_ = (seg == 1) ? Bgl : Bgh;
        uint32_t tA = sb + b * 32768;
        uint32_t tB = tA + 16384;
#pragma unroll
        for (int p = 0; p < 4; p++) {
            int row = lrow + p * 32;
            uint32_t off = SWZ((uint32_t)(row * 128 + lch * 16));
            cp16(tA + off, As_ + (long)(m0 + row) * K + koff + lch * 8);
        }
#pragma unroll
        for (int p = 0; p < 4; p++) {
            int row = lrow + p * 32;
            uint32_t off = SWZ((uint32_t)(row * 128 + lch * 16));
            cp16(tB + off, Bs_ + (long)(n0 + row) * K + koff + lch * 8);
        }
        cp_commit();
    };

    load_tile(0, 0);

    for (int it = 0; it < NT; ++it) {
        cp_wait0();
        __syncthreads();
        if (it + 1 < NT) load_tile(it + 1, (it + 1) & 1);

        uint32_t tA = sb + (it & 1) * 32768;
        uint32_t tB = tA + 16384;

#pragma unroll
        for (int ks = 0; ks < 4; ks++) {
            uint32_t a[4][4];
#pragma unroll
            for (int mi = 0; mi < 4; mi++) {
                int row = wm * 64 + mi * 16 + (lane & 15);
                uint32_t off = (uint32_t)(row * 128 + (2 * ks + (lane >> 4)) * 16);
                ldmx4(a[mi], tA + SWZ(off));
            }
            uint32_t b[2][4];
#pragma unroll
            for (int nj = 0; nj < 2; nj++) {
                int row = wn * 32 + nj * 16 + (lane & 7) + ((lane >> 4) << 3);
                uint32_t off = (uint32_t)(row * 128 + (2 * ks + ((lane >> 3) & 1)) * 16);
                ldmx4(b[nj], tB + SWZ(off));
            }
#pragma unroll
            for (int mi = 0; mi < 4; mi++)
#pragma unroll
                for (int ni = 0; ni < 4; ni++)
                    mma16816(d[mi][ni], a[mi],
                             b[ni >> 1][(ni & 1) * 2], b[ni >> 1][(ni & 1) * 2 + 1]);
        }
        __syncthreads();
    }

    // ---- epilogue: stage to smem, coalesced stores + bias ----
    float* sf = (float*)smem;                    // 128 x 132
#pragma unroll
    for (int mi = 0; mi < 4; mi++)
#pragma unroll
        for (int ni = 0; ni < 4; ni++) {
            int row = wm * 64 + mi * 16 + (lane >> 2);
            int col = wn * 32 + ni * 8 + 2 * (lane & 3);
            *(float2*)&sf[row * 132 + col]       = make_float2(d[mi][ni][0], d[mi][ni][1]);
            *(float2*)&sf[(row + 8) * 132 + col] = make_float2(d[mi][ni][2], d[mi][ni][3]);
        }
    __syncthreads();
#pragma unroll
    for (int p = 0; p < 16; p++) {
        int lin = p * 256 + tid;
        int row = lin >> 5, q = (lin & 31) * 4;
        const float* sr = sf + row * 132 + q;
        int n = n0 + q;
        float4 o;
        o.x = sr[0] + bias[n + 0];
        o.y = sr[1] + bias[n + 1];
        o.z = sr[2] + bias[n + 2];
        o.w = sr[3] + bias[n + 3];
        long idx = (long)(m0 + row) * N + n;
        if (Chi) {
            union { bf16 b[4]; uint2 u; } hh, ll;
            hh.b[0] = __float2bfloat16_rn(o.x);
            hh.b[1] = __float2bfloat16_rn(o.y);
            hh.b[2] = __float2bfloat16_rn(o.z);
            hh.b[3] = __float2bfloat16_rn(o.w);
            ll.b[0] = __float2bfloat16_rn(o.x - __bfloat162float(hh.b[0]));
            ll.b[1] = __float2bfloat16_rn(o.y - __bfloat162float(hh.b[1]));
            ll.b[2] = __float2bfloat16_rn(o.z - __bfloat162float(hh.b[2]));
            ll.b[3] = __float2bfloat16_rn(o.w - __bfloat162float(hh.b[3]));
            *(uint2*)(Chi + idx) = hh.u;
            *(uint2*)(Clo + idx) = ll.u;
        } else {
            *(float4*)(C + idx) = o;
        }
    }
}

// ---------------- tensor-core attention over B axis, 3x-split ------------
// CTA: (qb, h, t); 256 thr / 8 warps, each warp m16 query rows.
// SMEM: Qh|Ql (128x64 each, 32KB) + Kh|Kl|Vh|Vl (128x64 each, 64KB) = 96KB.
#define ATTN_SMEM_BYTES (98304)

__global__ __launch_bounds__(256, 2)
void attn_tc(const bf16* __restrict__ qh, const bf16* __restrict__ ql,
             bf16* __restrict__ ctxh, bf16* __restrict__ ctxl)
{
    extern __shared__ __align__(1024) char smem[];
    const uint32_t sb = smem_to_u32(smem);
    const uint32_t sQh = sb,          sQl = sb + 16384;
    const uint32_t sKh = sb + 32768,  sKl = sb + 49152;
    const uint32_t sVh = sb + 65536,  sVl = sb + 81920;

    const int qb = blockIdx.x, h = blockIdx.y, t = blockIdx.z;
    const int tid = threadIdx.x;
    const int w = tid >> 5, lane = tid & 31;
    const long rs = QKV_N;
    const bf16* bh = qh + (long)t * B_DIM * rs + h * HD_DIM;
    const bf16* bl = ql + (long)t * B_DIM * rs + h * HD_DIM;

    // loader mapping: 2 threads per 128B row, 4 cp16 each
    const int lrow = tid >> 1, lc0 = (tid & 1) * 4;

    // Q tiles (rows qb*128..)
    {
        const bf16* srcH = bh + (long)(qb * 128 + lrow) * rs;
        const bf16* srcL = bl + (long)(qb * 128 + lrow) * rs;
#pragma unroll
        for (int c = 0; c < 4; c++) {
            uint32_t off = SWZ((uint32_t)(lrow * 128 + (lc0 + c) * 16));
            cp16(sQh + off, srcH + (lc0 + c) * 8);
            cp16(sQl + off, srcL + (lc0 + c) * 8);
        }
    }
    auto load_kv = [&](int kb) {
        const bf16* kH = bh + D_DIM + (long)(kb * 128 + lrow) * rs;
        const bf16* kL = bl + D_DIM + (long)(kb * 128 + lrow) * rs;
        const bf16* vH = bh + 2 * D_DIM + (long)(kb * 128 + lrow) * rs;
        const bf16* vL = bl + 2 * D_DIM + (long)(kb * 128 + lrow) * rs;
#pragma unroll
        for (int c = 0; c < 4; c++) {
            uint32_t off = SWZ((uint32_t)(lrow * 128 + (lc0 + c) * 16));
            cp16(sKh + off, kH + (lc0 + c) * 8);
            cp16(sKl + off, kL + (lc0 + c) * 8);
            cp16(sVh + off, vH + (lc0 + c) * 8);
            cp16(sVl + off, vL + (lc0 + c) * 8);
        }
        cp_commit();
    };

    load_kv(0);
    cp_wait0();
    __syncthreads();

    float ctx[8][4];
#pragma unroll
    for (int f = 0; f < 8; f++)
#pragma unroll
        for (int e = 0; e < 4; e++) ctx[f][e] = 0.f;
    float esum0 = 0.f, esum1 = 0.f;
    const float SCL = 0.125f * 1.44269504f;   // log2(e)/sqrt(64)

    for (int kb = 0; kb < 4; kb++) {
#pragma unroll 1
        for (int half = 0; half < 2; half++) {
            const int hrow = half * 64;
            float s[8][4];
#pragma unroll
            for (int f = 0; f < 8; f++)
#pragma unroll
                for (int e = 0; e < 4; e++) s[f][e] = 0.f;

            // ---- S = Q K^T (3 splits), m16 x n64 ----
#pragma unroll
            for (int ks = 0; ks < 4; ks++) {
                uint32_t Ah[4], Al[4];
                {
                    int arow = w * 16 + (lane & 15);
                    uint32_t off = SWZ((uint32_t)(arow * 128 + (2 * ks + (lane >> 4)) * 16));
                    ldmx4(Ah, sQh + off);
                    ldmx4(Al, sQl + off);
                }
#pragma unroll
                for (int nj = 0; nj < 4; nj++) {
                    int brow = hrow + nj * 16 + (lane & 7) + ((lane >> 4) << 3);
                    uint32_t off = SWZ((uint32_t)(brow * 128 + (2 * ks + ((lane >> 3) & 1)) * 16));
                    uint32_t Bh[4], Bl[4];
                    ldmx4(Bh, sKh + off);
                    ldmx4(Bl, sKl + off);
                    mma16816(s[2 * nj],     Ah, Bh[0], Bh[1]);
                    mma16816(s[2 * nj + 1], Ah, Bh[2], Bh[3]);
                    mma16816(s[2 * nj],     Ah, Bl[0], Bl[1]);
                    mma16816(s[2 * nj + 1], Ah, Bl[2], Bl[3]);
                    mma16816(s[2 * nj],     Al, Bh[0], Bh[1]);
                    mma16816(s[2 * nj + 1], Al, Bh[2], Bh[3]);
                }
            }

            // ---- exp + row-sum ----
#pragma unroll
            for (int f = 0; f < 8; f++) {
                s[f][0] = fast_ex2(s[f][0] * SCL);
                s[f][1] = fast_ex2(s[f][1] * SCL);
                s[f][2] = fast_ex2(s[f][2] * SCL);
                s[f][3] = fast_ex2(s[f][3] * SCL);
                esum0 += s[f][0] + s[f][1];
                esum1 += s[f][2] + s[f][3];
            }

            // ---- ctx += P V (3 splits) ----
#pragma unroll
            for (int ks = 0; ks < 4; ks++) {
                uint32_t Ph[4], Pl[4];
                hilo_pack(s[2 * ks][0],     s[2 * ks][1],     Ph[0], Pl[0]);
                hilo_pack(s[2 * ks][2],     s[2 * ks][3],     Ph[1], Pl[1]);
                hilo_pack(s[2 * ks + 1][0], s[2 * ks + 1][1], Ph[2], Pl[2]);
                hilo_pack(s[2 * ks + 1][2], s[2 * ks + 1][3], Ph[3], Pl[3]);
#pragma unroll
                for (int n0 = 0; n0 < 4; n0++) {
                    int vrow = hrow + ks * 16 + (lane & 7) + (((lane >> 3) & 1) << 3);
                    uint32_t off = SWZ((uint32_t)(vrow * 128 + (n0 * 16 + (lane >> 4) * 8) * 2));
                    uint32_t Vh_[4], Vl_[4];
                    ldmx4t(Vh_, sVh + off);
                    ldmx4t(Vl_, sVl + off);
                    mma16816(ctx[2 * n0],     Ph, Vh_[0], Vh_[1]);
                    mma16816(ctx[2 * n0 + 1], Ph, Vh_[2], Vh_[3]);
                    mma16816(ctx[2 * n0],     Ph, Vl_[0], Vl_[1]);
                    mma16816(ctx[2 * n0 + 1], Ph, Vl_[2], Vl_[3]);
                    mma16816(ctx[2 * n0],     Pl, Vh_[0], Vh_[1]);
                    mma16816(ctx[2 * n0 + 1], Pl, Vh_[2], Vh_[3]);
                }
            }
        }
        __syncthreads();
        if (kb < 3) {
            load_kv(kb + 1);
            cp_wait0();
            __syncthreads();
        }
    }

    // ---- normalize + write ctx hi/lo ----
    esum0 += __shfl_xor_sync(0xffffffffu, esum0, 1);
    esum0 += __shfl_xor_sync(0xffffffffu, esum0, 2);
    esum1 += __shfl_xor_sync(0xffffffffu, esum1, 1);
    esum1 += __shfl_xor_sync(0xffffffffu, esum1, 2);
    float inv0 = 1.f / esum0, inv1 = 1.f / esum1;

    long row0 = ((long)t * B_DIM + qb * 128 + w * 16 + (lane >> 2)) * D_DIM + h * HD_DIM;
    long row1 = row0 + 8 * D_DIM;
#pragma unroll
    for (int f = 0; f < 8; f++) {
        int col = f * 8 + 2 * (lane & 3);
        uint32_t hw, lw;
        hilo_pack(ctx[f][0] * inv0, ctx[f][1] * inv0, hw, lw);
        *(uint32_t*)(ctxh + row0 + col) = hw;
        *(uint32_t*)(ctxl + row0 + col) = lw;
        hilo_pack(ctx[f][2] * inv1, ctx[f][3] * inv1, hw, lw);
        *(uint32_t*)(ctxh + row1 + col) = hw;
        *(uint32_t*)(ctxl + row1 + col) = lw;
    }
}

// ---------------- epilogue kernels ----------------
__global__ __launch_bounds__(256)
void rownorm_kernel(const float* __restrict__ o, float* __restrict__ invn)
{
    int row = blockIdx.x * 8 + (threadIdx.x >> 5);
    int lane = threadIdx.x & 31;
    const float* p = o + (long)row * D_DIM;
    float ss = 0.f;
#pragma unroll
    for (int k = 0; k < 6; k++) {
        float4 v = *(const float4*)(p + lane * 4 + k * 128);
        ss += v.x * v.x + v.y * v.y + v.z * v.z + v.w * v.w;
    }
#pragma unroll
    for (int off = 16; off; off >>= 1) ss += __shfl_xor_sync(0xffffffffu, ss, off);
    if (lane == 0) invn[row] = 1.f / fmaxf(sqrtf(ss), 1e-8f);
}

__global__ __launch_bounds__(256)
void meanvec_kernel(const float* __restrict__ o, const float* __restrict__ invn,
                    float* __restrict__ svec)
{
    int t = blockIdx.y;
    int d = blockIdx.x * 256 + threadIdx.x;
    const float* p = o + (long)t * B_DIM * D_DIM + d;
    const float* iv = invn + t * B_DIM;
    float s = 0.f;
#pragma unroll 8
    for (int b = 0; b < B_DIM; b++) s += p[(long)b * D_DIM] * iv[b];
    svec[t * D_DIM + d] = s;
}

__global__ __launch_bounds__(256)
void adj_kernel(const float* __restrict__ o, const float* __restrict__ invn,
                const float* __restrict__ svec, float* __restrict__ adj)
{
    int row = blockIdx.x * 8 + (threadIdx.x >> 5);
    int lane = threadIdx.x & 31;
    int t = row >> 9;
    const float* p = o + (long)row * D_DIM;
    const float* sv = svec + t * D_DIM;
    float acc = 0.f;
#pragma unroll
    for (int k = 0; k < 6; k++) {
        float4 v = *(const float4*)(p + lane * 4 + k * 128);
        float4 s = *(const float4*)(sv + lane * 4 + k * 128);
        acc += v.x * s.x + v.y * s.y + v.z * s.z + v.w * s.w;
    }
#pragma unroll
    for (int off = 16; off; off >>= 1) acc += __shfl_xor_sync(0xffffffffu, acc, off);
    if (lane == 0) adj[row] = acc * invn[row] * (1.0f / (float)B_DIM);
}

// ---------------- launch ----------------
extern "C" void kernel_launch(void* const* d_in, const int* in_sizes, int n_in,
                              void* d_out, int out_size)
{
    const float* x  = (const float*)d_in[0];   // node_embs (T,B,D)
    const float* w1 = (const float*)d_in[1];   // in_proj_w (3D,D)
    const float* b1 = (const float*)d_in[2];   // in_proj_b (3D)
    const float* w2 = (const float*)d_in[3];   // out_proj_w (D,D)
    const float* b2 = (const float*)d_in[4];   // out_proj_b (D)
    float* adj = (float*)d_out;                // (T,B,1)

    float *outb, *invn, *svec;
    bf16 *qkvh, *qkvl, *xh, *xl, *chh, *cl, *w1h, *w1l, *w2h, *w2l;
    cudaGetSymbolAddress((void**)&outb, g_out);
    cudaGetSymbolAddress((void**)&invn, g_invn);
    cudaGetSymbolAddress((void**)&svec, g_svec);
    cudaGetSymbolAddress((void**)&qkvh, g_qkvh);
    cudaGetSymbolAddress((void**)&qkvl, g_qkvl);
    cudaGetSymbolAddress((void**)&xh,  g_xh);
    cudaGetSymbolAddress((void**)&xl,  g_xl);
    cudaGetSymbolAddress((void**)&chh, g_ch);
    cudaGetSymbolAddress((void**)&cl,  g_cl);
    cudaGetSymbolAddress((void**)&w1h, g_w1h);
    cudaGetSymbolAddress((void**)&w1l, g_w1l);
    cudaGetSymbolAddress((void**)&w2h, g_w2h);
    cudaGetSymbolAddress((void**)&w2l, g_w2l);

    cudaFuncSetAttribute(gemm_tc, cudaFuncAttributeMaxDynamicSharedMemorySize,
                         GEMM_SMEM_BYTES);
    cudaFuncSetAttribute(attn_tc, cudaFuncAttributeMaxDynamicSharedMemorySize,
                         ATTN_SMEM_BYTES);

    // 0) bf16 hi/lo splits of x, w1, w2
    {
        int n4 = ROWS * D_DIM / 4;
        cvt_hilo<<<(n4 + 255) / 256, 256>>>(x, xh, xl, n4);
    }
    {
        int n4 = QKV_N * D_DIM / 4;
        cvt_hilo<<<(n4 + 255) / 256, 256>>>(w1, w1h, w1l, n4);
    }
    {
        int n4 = D_DIM * D_DIM / 4;
        cvt_hilo<<<(n4 + 255) / 256, 256>>>(w2, w2h, w2l, n4);
    }

    // 1) qkv = x @ W1^T + b1  -> bf16 hi/lo directly
    gemm_tc<<<dim3(QKV_N / 128, ROWS / 128), 256, GEMM_SMEM_BYTES>>>(
        xh, xl, w1h, w1l, b1, nullptr, qkvh, qkvl, QKV_N, D_DIM);

    // 2) tensor-core attention -> ctx hi/lo directly
    attn_tc<<<dim3(B_DIM / 128, H_DIM, T_DIM), 256, ATTN_SMEM_BYTES>>>(
        qkvh, qkvl, chh, cl);

    // 3) out = ctx @ W2^T + b2 (fp32 out)
    gemm_tc<<<dim3(D_DIM / 128, ROWS / 128), 256, GEMM_SMEM_BYTES>>>(
        chh, cl, w2h, w2l, b2, outb, nullptr, nullptr, D_DIM, D_DIM);

    // 4-6) cosine-sim epilogue (collapsed via mean-vector identity)
    rownorm_kernel<<<ROWS / 8, 256>>>(outb, invn);
    meanvec_kernel<<<dim3(D_DIM / 256, T_DIM), 256>>>(outb, invn, svec);
    adj_kernel<<<ROWS / 8, 256>>>(outb, invn, svec, adj);
}

// round 15
// speedup vs baseline: 3.1535x; 1.5841x over previous
#include <cuda_runtime.h>
#include <cuda_bf16.h>
#include <cstdint>

// Shapes: T=64, B=512, D=768, H=12, HD=64
#define T_DIM 64
#define B_DIM 512
#define D_DIM 768
#define H_DIM 12
#define HD_DIM 64
#define ROWS (T_DIM * B_DIM)          // 32768
#define QKV_N (3 * D_DIM)             // 2304

typedef unsigned long long u64;
typedef __nv_bfloat16 bf16;

__device__ __forceinline__ uint32_t smem_to_u32(const void* p) {
    uint32_t a;
    asm("{ .reg .u64 t; cvta.to.shared.u64 t, %1; cvt.u32.u64 %0, t; }"
        : "=r"(a) : "l"(p));
    return a;
}

#define SWZ(x) ((x) ^ (((x) >> 3) & 0x70))

__device__ __forceinline__ void cp16(uint32_t dst, const void* src) {
    asm volatile("cp.async.cg.shared.global [%0], [%1], 16;"
                 :: "r"(dst), "l"(src));
}
__device__ __forceinline__ void cp_commit() {
    asm volatile("cp.async.commit_group;");
}
__device__ __forceinline__ void cp_wait0() {
    asm volatile("cp.async.wait_group 0;");
}
__device__ __forceinline__ void cp_wait1() {
    asm volatile("cp.async.wait_group 1;");
}

__device__ __forceinline__ void ldmx4(uint32_t* r, uint32_t addr) {
    asm volatile("ldmatrix.sync.aligned.m8n8.x4.shared.b16 {%0,%1,%2,%3}, [%4];"
                 : "=r"(r[0]), "=r"(r[1]), "=r"(r[2]), "=r"(r[3]) : "r"(addr));
}
__device__ __forceinline__ void ldmx4t(uint32_t* r, uint32_t addr) {
    asm volatile("ldmatrix.sync.aligned.m8n8.x4.trans.shared.b16 {%0,%1,%2,%3}, [%4];"
                 : "=r"(r[0]), "=r"(r[1]), "=r"(r[2]), "=r"(r[3]) : "r"(addr));
}
__device__ __forceinline__ void mma16816(float* d, const uint32_t* a,
                                         uint32_t b0, uint32_t b1) {
    asm volatile(
        "mma.sync.aligned.m16n8k16.row.col.f32.bf16.bf16.f32 "
        "{%0,%1,%2,%3}, {%4,%5,%6,%7}, {%8,%9}, {%0,%1,%2,%3};"
        : "+f"(d[0]), "+f"(d[1]), "+f"(d[2]), "+f"(d[3])
        : "r"(a[0]), "r"(a[1]), "r"(a[2]), "r"(a[3]), "r"(b0), "r"(b1));
}

__device__ __forceinline__ float fast_ex2(float x) {
    float r;
    asm("ex2.approx.ftz.f32 %0, %1;" : "=f"(r) : "f"(x));
    return r;
}
__device__ __forceinline__ void hilo_pack(float x, float y, uint32_t& hw, uint32_t& lw) {
    union { bf16 b[2]; uint32_t u; } H, L;
    H.b[0] = __float2bfloat16_rn(x);
    H.b[1] = __float2bfloat16_rn(y);
    L.b[0] = __float2bfloat16_rn(x - __bfloat162float(H.b[0]));
    L.b[1] = __float2bfloat16_rn(y - __bfloat162float(H.b[1]));
    hw = H.u; lw = L.u;
}

// ---------------- scratch (device globals; no allocations) ----------------
__device__ float g_out[(size_t)ROWS * D_DIM];
__device__ float g_invn[ROWS];
__device__ float g_svec[T_DIM * D_DIM];
__device__ __align__(16) bf16 g_qkvh[(size_t)ROWS * QKV_N];
__device__ __align__(16) bf16 g_qkvl[(size_t)ROWS * QKV_N];
__device__ __align__(16) bf16 g_xh[(size_t)ROWS * D_DIM];
__device__ __align__(16) bf16 g_xl[(size_t)ROWS * D_DIM];
__device__ __align__(16) bf16 g_ch[(size_t)ROWS * D_DIM];
__device__ __align__(16) bf16 g_cl[(size_t)ROWS * D_DIM];
__device__ __align__(16) bf16 g_w1h[(size_t)QKV_N * D_DIM];
__device__ __align__(16) bf16 g_w1l[(size_t)QKV_N * D_DIM];
__device__ __align__(16) bf16 g_w2h[(size_t)D_DIM * D_DIM];
__device__ __align__(16) bf16 g_w2l[(size_t)D_DIM * D_DIM];

// ---------------- fp32 -> bf16 hi/lo split ----------------
__global__ __launch_bounds__(256)
void cvt_hilo(const float* __restrict__ x, bf16* __restrict__ h,
              bf16* __restrict__ l, int n4)
{
    int i = blockIdx.x * 256 + threadIdx.x;
    if (i >= n4) return;
    float4 v = ((const float4*)x)[i];
    union { bf16 b[4]; uint2 u; } ph, pl;
    ph.b[0] = __float2bfloat16_rn(v.x);
    ph.b[1] = __float2bfloat16_rn(v.y);
    ph.b[2] = __float2bfloat16_rn(v.z);
    ph.b[3] = __float2bfloat16_rn(v.w);
    pl.b[0] = __float2bfloat16_rn(v.x - __bfloat162float(ph.b[0]));
    pl.b[1] = __float2bfloat16_rn(v.y - __bfloat162float(ph.b[1]));
    pl.b[2] = __float2bfloat16_rn(v.z - __bfloat162float(ph.b[2]));
    pl.b[3] = __float2bfloat16_rn(v.w - __bfloat162float(ph.b[3]));
    ((uint2*)h)[i] = ph.u;
    ((uint2*)l)[i] = pl.u;
}

// ------------- mma.sync bf16 GEMM-NT: C = A*B^T + bias, 3x-split ----------
// Virtual K = 3*K via segments (Ah,Bh), (Ah,Bl), (Al,Bh).
// Tile 128x128, BK=64, 256 threads (8 warps, 2x4), warp tile 64x32.
// 3-stage cp.async pipeline (3 x 32KB buffers), single sync per K-tile.
#define GEMM_SMEM_BYTES (3 * 32768)

__global__ __launch_bounds__(256)
void gemm_tc(const bf16* __restrict__ Agh, const bf16* __restrict__ Agl,
             const bf16* __restrict__ Bgh, const bf16* __restrict__ Bgl,
             const float* __restrict__ bias, float* __restrict__ C,
             bf16* __restrict__ Chi, bf16* __restrict__ Clo,
             int N, int K)
{
    extern __shared__ __align__(1024) char smem[];
    const uint32_t sb = smem_to_u32(smem);
    const int tid = threadIdx.x;
    const int wid = tid >> 5, lane = tid & 31;
    const int wm = wid >> 2, wn = wid & 3;       // 2 x 4 warp grid
    const int m0 = blockIdx.y * 128, n0 = blockIdx.x * 128;

    const int NSEG_T = K / 64;
    const int NT = 3 * NSEG_T;

    float d[4][4][4];
#pragma unroll
    for (int i = 0; i < 4; i++)
#pragma unroll
        for (int j = 0; j < 4; j++)
#pragma unroll
            for (int k = 0; k < 4; k++) d[i][j][k] = 0.f;

    const int lrow = tid >> 3, lch = tid & 7;

    auto load_tile = [&](int it, int b) {
        int seg = it / NSEG_T;
        long koff = (long)(it - seg * NSEG_T) * 64;
        const bf16* As_ = (seg < 2) ? Agh : Agl;
        const bf16* Bs_ = (seg == 1) ? Bgl : Bgh;
        uint32_t tA = sb + b * 32768;
        uint32_t tB = tA + 16384;
#pragma unroll
        for (int p = 0; p < 4; p++) {
            int row = lrow + p * 32;
            uint32_t off = SWZ((uint32_t)(row * 128 + lch * 16));
            cp16(tA + off, As_ + (long)(m0 + row) * K + koff + lch * 8);
        }
#pragma unroll
        for (int p = 0; p < 4; p++) {
            int row = lrow + p * 32;
            uint32_t off = SWZ((uint32_t)(row * 128 + lch * 16));
            cp16(tB + off, Bs_ + (long)(n0 + row) * K + koff + lch * 8);
        }
        cp_commit();
    };

    load_tile(0, 0);
    load_tile(1, 1);

    int buf = 0;
    for (int it = 0; it < NT; ++it) {
        if (it + 2 < NT) cp_wait1(); else cp_wait0();
        __syncthreads();
        // 3 buffers: buffer (it+2)%3 is neither read now (it%3) nor in flight
        // ((it+1)%3), and the barrier above retired all reads of it from it-1.
        if (it + 2 < NT) load_tile(it + 2, (it + 2) % 3);

        uint32_t tA = sb + buf * 32768;
        uint32_t tB = tA + 16384;

#pragma unroll
        for (int ks = 0; ks < 4; ks++) {
            uint32_t a[4][4];
#pragma unroll
            for (int mi = 0; mi < 4; mi++) {
                int row = wm * 64 + mi * 16 + (lane & 15);
                uint32_t off = (uint32_t)(row * 128 + (2 * ks + (lane >> 4)) * 16);
                ldmx4(a[mi], tA + SWZ(off));
            }
            uint32_t b[2][4];
#pragma unroll
            for (int nj = 0; nj < 2; nj++) {
                int row = wn * 32 + nj * 16 + (lane & 7) + ((lane >> 4) << 3);
                uint32_t off = (uint32_t)(row * 128 + (2 * ks + ((lane >> 3) & 1)) * 16);
                ldmx4(b[nj], tB + SWZ(off));
            }
#pragma unroll
            for (int mi = 0; mi < 4; mi++)
#pragma unroll
                for (int ni = 0; ni < 4; ni++)
                    mma16816(d[mi][ni], a[mi],
                             b[ni >> 1][(ni & 1) * 2], b[ni >> 1][(ni & 1) * 2 + 1]);
        }
        buf = (buf + 1 == 3) ? 0 : buf + 1;
    }
    __syncthreads();

    // ---- epilogue: stage to smem, coalesced stores + bias ----
    float* sf = (float*)smem;                    // 128 x 132
#pragma unroll
    for (int mi = 0; mi < 4; mi++)
#pragma unroll
        for (int ni = 0; ni < 4; ni++) {
            int row = wm * 64 + mi * 16 + (lane >> 2);
            int col = wn * 32 + ni * 8 + 2 * (lane & 3);
            *(float2*)&sf[row * 132 + col]       = make_float2(d[mi][ni][0], d[mi][ni][1]);
            *(float2*)&sf[(row + 8) * 132 + col] = make_float2(d[mi][ni][2], d[mi][ni][3]);
        }
    __syncthreads();
#pragma unroll
    for (int p = 0; p < 16; p++) {
        int lin = p * 256 + tid;
        int row = lin >> 5, q = (lin & 31) * 4;
        const float* sr = sf + row * 132 + q;
        int n = n0 + q;
        float4 o;
        o.x = sr[0] + bias[n + 0];
        o.y = sr[1] + bias[n + 1];
        o.z = sr[2] + bias[n + 2];
        o.w = sr[3] + bias[n + 3];
        long idx = (long)(m0 + row) * N + n;
        if (Chi) {
            union { bf16 b[4]; uint2 u; } hh, ll;
            hh.b[0] = __float2bfloat16_rn(o.x);
            hh.b[1] = __float2bfloat16_rn(o.y);
            hh.b[2] = __float2bfloat16_rn(o.z);
            hh.b[3] = __float2bfloat16_rn(o.w);
            ll.b[0] = __float2bfloat16_rn(o.x - __bfloat162float(hh.b[0]));
            ll.b[1] = __float2bfloat16_rn(o.y - __bfloat162float(hh.b[1]));
            ll.b[2] = __float2bfloat16_rn(o.z - __bfloat162float(hh.b[2]));
            ll.b[3] = __float2bfloat16_rn(o.w - __bfloat162float(hh.b[3]));
            *(uint2*)(Chi + idx) = hh.u;
            *(uint2*)(Clo + idx) = ll.u;
        } else {
            *(float4*)(C + idx) = o;
        }
    }
}

// ---------------- tensor-core attention over B axis, 3x-split ------------
// CTA: (qb, h, t); 256 thr / 8 warps, each warp m16 query rows.
// KV processed in 8 blocks of 64 rows, DOUBLE-BUFFERED cp.async.
// SMEM: Qh|Ql (128x64, 32KB) + 2 x [Kh|Kl|Vh|Vl](64x64 each, 32KB) = 96KB.
#define ATTN_SMEM_BYTES (98304)

__global__ __launch_bounds__(256, 2)
void attn_tc(const bf16* __restrict__ qh, const bf16* __restrict__ ql,
             bf16* __restrict__ ctxh, bf16* __restrict__ ctxl)
{
    extern __shared__ __align__(1024) char smem[];
    const uint32_t sb = smem_to_u32(smem);
    const uint32_t sQh = sb, sQl = sb + 16384;

    const int qb = blockIdx.x, h = blockIdx.y, t = blockIdx.z;
    const int tid = threadIdx.x;
    const int w = tid >> 5, lane = tid & 31;
    const long rs = QKV_N;
    const bf16* bh = qh + (long)t * B_DIM * rs + h * HD_DIM;
    const bf16* bl = ql + (long)t * B_DIM * rs + h * HD_DIM;

    // Q loader: 2 threads per 128B row
    {
        const int lrow = tid >> 1, lc0 = (tid & 1) * 4;
        const bf16* srcH = bh + (long)(qb * 128 + lrow) * rs;
        const bf16* srcL = bl + (long)(qb * 128 + lrow) * rs;
#pragma unroll
        for (int c = 0; c < 4; c++) {
            uint32_t off = SWZ((uint32_t)(lrow * 128 + (lc0 + c) * 16));
            cp16(sQh + off, srcH + (lc0 + c) * 8);
            cp16(sQl + off, srcL + (lc0 + c) * 8);
        }
    }
    // KV loader: 64-row block into buffer bb; 4 threads per row, 2 chunks each
    const int krow = tid >> 2, kc0 = (tid & 3) * 2;
    auto load_kv = [&](int blk, int bb) {
        uint32_t base = sb + 32768 + bb * 32768;
        const bf16* kH = bh + D_DIM + (long)(blk * 64 + krow) * rs;
        const bf16* kL = bl + D_DIM + (long)(blk * 64 + krow) * rs;
        const bf16* vH = bh + 2 * D_DIM + (long)(blk * 64 + krow) * rs;
        const bf16* vL = bl + 2 * D_DIM + (long)(blk * 64 + krow) * rs;
#pragma unroll
        for (int c = 0; c < 2; c++) {
            uint32_t off = SWZ((uint32_t)(krow * 128 + (kc0 + c) * 16));
            cp16(base + off,         kH + (kc0 + c) * 8);
            cp16(base + 8192 + off,  kL + (kc0 + c) * 8);
            cp16(base + 16384 + off, vH + (kc0 + c) * 8);
            cp16(base + 24576 + off, vL + (kc0 + c) * 8);
        }
        cp_commit();
    };

    load_kv(0, 0);   // group0 = Q + KV0
    load_kv(1, 1);

    float ctx[8][4];
#pragma unroll
    for (int f = 0; f < 8; f++)
#pragma unroll
        for (int e = 0; e < 4; e++) ctx[f][e] = 0.f;
    float esum0 = 0.f, esum1 = 0.f;
    const float SCL = 0.125f * 1.44269504f;   // log2(e)/sqrt(64)

    for (int blk = 0; blk < 8; blk++) {
        if (blk + 2 < 8) cp_wait1(); else cp_wait0();
        __syncthreads();
        const uint32_t base = sb + 32768 + (blk & 1) * 32768;
        const uint32_t sKh = base, sKl = base + 8192;
        const uint32_t sVh = base + 16384, sVl = base + 24576;

        float s[8][4];
#pragma unroll
        for (int f = 0; f < 8; f++)
#pragma unroll
            for (int e = 0; e < 4; e++) s[f][e] = 0.f;

        // ---- S = Q K^T (3 splits), m16 x n64 ----
#pragma unroll
        for (int ks = 0; ks < 4; ks++) {
            uint32_t Ah[4], Al[4];
            {
                int arow = w * 16 + (lane & 15);
                uint32_t off = SWZ((uint32_t)(arow * 128 + (2 * ks + (lane >> 4)) * 16));
                ldmx4(Ah, sQh + off);
                ldmx4(Al, sQl + off);
            }
#pragma unroll
            for (int nj = 0; nj < 4; nj++) {
                int brow = nj * 16 + (lane & 7) + ((lane >> 4) << 3);
                uint32_t off = SWZ((uint32_t)(brow * 128 + (2 * ks + ((lane >> 3) & 1)) * 16));
                uint32_t Bh[4], Bl[4];
                ldmx4(Bh, sKh + off);
                ldmx4(Bl, sKl + off);
                mma16816(s[2 * nj],     Ah, Bh[0], Bh[1]);
                mma16816(s[2 * nj + 1], Ah, Bh[2], Bh[3]);
                mma16816(s[2 * nj],     Ah, Bl[0], Bl[1]);
                mma16816(s[2 * nj + 1], Ah, Bl[2], Bl[3]);
                mma16816(s[2 * nj],     Al, Bh[0], Bh[1]);
                mma16816(s[2 * nj + 1], Al, Bh[2], Bh[3]);
            }
        }

        // ---- exp + row-sum ----
#pragma unroll
        for (int f = 0; f < 8; f++) {
            s[f][0] = fast_ex2(s[f][0] * SCL);
            s[f][1] = fast_ex2(s[f][1] * SCL);
            s[f][2] = fast_ex2(s[f][2] * SCL);
            s[f][3] = fast_ex2(s[f][3] * SCL);
            esum0 += s[f][0] + s[f][1];
            esum1 += s[f][2] + s[f][3];
        }

        // ---- ctx += P V (3 splits) ----
#pragma unroll
        for (int ks = 0; ks < 4; ks++) {
            uint32_t Ph[4], Pl[4];
            hilo_pack(s[2 * ks][0],     s[2 * ks][1],     Ph[0], Pl[0]);
            hilo_pack(s[2 * ks][2],     s[2 * ks][3],     Ph[1], Pl[1]);
            hilo_pack(s[2 * ks + 1][0], s[2 * ks + 1][1], Ph[2], Pl[2]);
            hilo_pack(s[2 * ks + 1][2], s[2 * ks + 1][3], Ph[3], Pl[3]);
#pragma unroll
            for (int n0 = 0; n0 < 4; n0++) {
                int vrow = ks * 16 + (lane & 7) + (((lane >> 3) & 1) << 3);
                uint32_t off = SWZ((uint32_t)(vrow * 128 + (n0 * 16 + (lane >> 4) * 8) * 2));
                uint32_t Vh_[4], Vl_[4];
                ldmx4t(Vh_, sVh + off);
                ldmx4t(Vl_, sVl + off);
                mma16816(ctx[2 * n0],     Ph, Vh_[0], Vh_[1]);
                mma16816(ctx[2 * n0 + 1], Ph, Vh_[2], Vh_[3]);
                mma16816(ctx[2 * n0],     Ph, Vl_[0], Vl_[1]);
                mma16816(ctx[2 * n0 + 1], Ph, Vl_[2], Vl_[3]);
                mma16816(ctx[2 * n0],     Pl, Vh_[0], Vh_[1]);
                mma16816(ctx[2 * n0 + 1], Pl, Vh_[2], Vh_[3]);
            }
        }

        __syncthreads();   // all reads of buffer blk&1 retired before refill
        if (blk + 2 < 8) load_kv(blk + 2, blk & 1);
    }

    // ---- normalize + write ctx hi/lo ----
    esum0 += __shfl_xor_sync(0xffffffffu, esum0, 1);
    esum0 += __shfl_xor_sync(0xffffffffu, esum0, 2);
    esum1 += __shfl_xor_sync(0xffffffffu, esum1, 1);
    esum1 += __shfl_xor_sync(0xffffffffu, esum1, 2);
    float inv0 = 1.f / esum0, inv1 = 1.f / esum1;

    long row0 = ((long)t * B_DIM + qb * 128 + w * 16 + (lane >> 2)) * D_DIM + h * HD_DIM;
    long row1 = row0 + 8 * D_DIM;
#pragma unroll
    for (int f = 0; f < 8; f++) {
        int col = f * 8 + 2 * (lane & 3);
        uint32_t hw, lw;
        hilo_pack(ctx[f][0] * inv0, ctx[f][1] * inv0, hw, lw);
        *(uint32_t*)(ctxh + row0 + col) = hw;
        *(uint32_t*)(ctxl + row0 + col) = lw;
        hilo_pack(ctx[f][2] * inv1, ctx[f][3] * inv1, hw, lw);
        *(uint32_t*)(ctxh + row1 + col) = hw;
        *(uint32_t*)(ctxl + row1 + col) = lw;
    }
}

// ---------------- epilogue kernels ----------------
__global__ __launch_bounds__(256)
void rownorm_kernel(const float* __restrict__ o, float* __restrict__ invn)
{
    int row = blockIdx.x * 8 + (threadIdx.x >> 5);
    int lane = threadIdx.x & 31;
    const float* p = o + (long)row * D_DIM;
    float ss = 0.f;
#pragma unroll
    for (int k = 0; k < 6; k++) {
        float4 v = *(const float4*)(p + lane * 4 + k * 128);
        ss += v.x * v.x + v.y * v.y + v.z * v.z + v.w * v.w;
    }
#pragma unroll
    for (int off = 16; off; off >>= 1) ss += __shfl_xor_sync(0xffffffffu, ss, off);
    if (lane == 0) invn[row] = 1.f / fmaxf(sqrtf(ss), 1e-8f);
}

__global__ __launch_bounds__(256)
void meanvec_kernel(const float* __restrict__ o, const float* __restrict__ invn,
                    float* __restrict__ svec)
{
    int t = blockIdx.y;
    int d = blockIdx.x * 256 + threadIdx.x;
    const float* p = o + (long)t * B_DIM * D_DIM + d;
    const float* iv = invn + t * B_DIM;
    float s = 0.f;
#pragma unroll 8
    for (int b = 0; b < B_DIM; b++) s += p[(long)b * D_DIM] * iv[b];
    svec[t * D_DIM + d] = s;
}

__global__ __launch_bounds__(256)
void adj_kernel(const float* __restrict__ o, const float* __restrict__ invn,
                const float* __restrict__ svec, float* __restrict__ adj)
{
    int row = blockIdx.x * 8 + (threadIdx.x >> 5);
    int lane = threadIdx.x & 31;
    int t = row >> 9;
    const float* p = o + (long)row * D_DIM;
    const float* sv = svec + t * D_DIM;
    float acc = 0.f;
#pragma unroll
    for (int k = 0; k < 6; k++) {
        float4 v = *(const float4*)(p + lane * 4 + k * 128);
        float4 s = *(const float4*)(sv + lane * 4 + k * 128);
        acc += v.x * s.x + v.y * s.y + v.z * s.z + v.w * s.w;
    }
#pragma unroll
    for (int off = 16; off; off >>= 1) acc += __shfl_xor_sync(0xffffffffu, acc, off);
    if (lane == 0) adj[row] = acc * invn[row] * (1.0f / (float)B_DIM);
}

// ---------------- launch ----------------
extern "C" void kernel_launch(void* const* d_in, const int* in_sizes, int n_in,
                              void* d_out, int out_size)
{
    const float* x  = (const float*)d_in[0];   // node_embs (T,B,D)
    const float* w1 = (const float*)d_in[1];   // in_proj_w (3D,D)
    const float* b1 = (const float*)d_in[2];   // in_proj_b (3D)
    const float* w2 = (const float*)d_in[3];   // out_proj_w (D,D)
    const float* b2 = (const float*)d_in[4];   // out_proj_b (D)
    float* adj = (float*)d_out;                // (T,B,1)

    float *outb, *invn, *svec;
    bf16 *qkvh, *qkvl, *xh, *xl, *chh, *cl, *w1h, *w1l, *w2h, *w2l;
    cudaGetSymbolAddress((void**)&outb, g_out);
    cudaGetSymbolAddress((void**)&invn, g_invn);
    cudaGetSymbolAddress((void**)&svec, g_svec);
    cudaGetSymbolAddress((void**)&qkvh, g_qkvh);
    cudaGetSymbolAddress((void**)&qkvl, g_qkvl);
    cudaGetSymbolAddress((void**)&xh,  g_xh);
    cudaGetSymbolAddress((void**)&xl,  g_xl);
    cudaGetSymbolAddress((void**)&chh, g_ch);
    cudaGetSymbolAddress((void**)&cl,  g_cl);
    cudaGetSymbolAddress((void**)&w1h, g_w1h);
    cudaGetSymbolAddress((void**)&w1l, g_w1l);
    cudaGetSymbolAddress((void**)&w2h, g_w2h);
    cudaGetSymbolAddress((void**)&w2l, g_w2l);

    cudaFuncSetAttribute(gemm_tc, cudaFuncAttributeMaxDynamicSharedMemorySize,
                         GEMM_SMEM_BYTES);
    cudaFuncSetAttribute(attn_tc, cudaFuncAttributeMaxDynamicSharedMemorySize,
                         ATTN_SMEM_BYTES);

    // 0) bf16 hi/lo splits of x, w1, w2
    {
        int n4 = ROWS * D_DIM / 4;
        cvt_hilo<<<(n4 + 255) / 256, 256>>>(x, xh, xl, n4);
    }
    {
        int n4 = QKV_N * D_DIM / 4;
        cvt_hilo<<<(n4 + 255) / 256, 256>>>(w1, w1h, w1l, n4);
    }
    {
        int n4 = D_DIM * D_DIM / 4;
        cvt_hilo<<<(n4 + 255) / 256, 256>>>(w2, w2h, w2l, n4);
    }

    // 1) qkv = x @ W1^T + b1  -> bf16 hi/lo directly
    gemm_tc<<<dim3(QKV_N / 128, ROWS / 128), 256, GEMM_SMEM_BYTES>>>(
        xh, xl, w1h, w1l, b1, nullptr, qkvh, qkvl, QKV_N, D_DIM);

    // 2) tensor-core attention (double-buffered KV) -> ctx hi/lo directly
    attn_tc<<<dim3(B_DIM / 128, H_DIM, T_DIM), 256, ATTN_SMEM_BYTES>>>(
        qkvh, qkvl, chh, cl);

    // 3) out = ctx @ W2^T + b2 (fp32 out)
    gemm_tc<<<dim3(D_DIM / 128, ROWS / 128), 256, GEMM_SMEM_BYTES>>>(
        chh, cl, w2h, w2l, b2, outb, nullptr, nullptr, D_DIM, D_DIM);

    // 4-6) cosine-sim epilogue (collapsed via mean-vector identity)
    rownorm_kernel<<<ROWS / 8, 256>>>(outb, invn);
    meanvec_kernel<<<dim3(D_DIM / 256, T_DIM), 256>>>(outb, invn, svec);
    adj_kernel<<<ROWS / 8, 256>>>(outb, invn, svec, adj);
}